// round 1
// baseline (speedup 1.0000x reference)
#include <cuda_runtime.h>
#include <cuda_bf16.h>
#include <math.h>

// Problem constants
#define N_TOK 8192
#define DDIM  2048
#define HDIM  2048
#define NEXP  8
#define TOPK  2
#define NT    (N_TOK * TOPK)   // 16384 token-copies

// GEMM tiling
#define BM 64
#define BN 64
#define BK 16
#define MAX_TILES (NT / BM + NEXP)  // 264 worst case

// -------- device scratch (allocation-free rule: device globals) ----------
__device__ float g_hidden[(size_t)NT * HDIM];  // 128 MiB
__device__ float g_out[(size_t)NT * DDIM];     // 128 MiB
__device__ int   g_perm[NT];    // perm[p] = copy index t occupying grouped slot p
__device__ int   g_slot[NT];    // slot[t] = p
__device__ int   g_counter[NEXP];
__device__ int   g_tile_e[MAX_TILES];
__device__ int   g_tile_row[MAX_TILES];   // first grouped-slot p of this m-tile
__device__ int   g_tile_end[MAX_TILES];   // end of this expert's bin
__device__ int   g_num_tiles;

// -------------------- setup: offsets + tile map ---------------------------
__global__ void setup_kernel(const int* __restrict__ bspe) {
    if (threadIdx.x != 0 || blockIdx.x != 0) return;
    int off = 0, t = 0;
    for (int e = 0; e < NEXP; e++) {
        int c = bspe[e];
        g_counter[e] = off;
        int end = off + c;
        for (int r = off; r < end; r += BM) {
            g_tile_e[t] = e; g_tile_row[t] = r; g_tile_end[t] = end; t++;
        }
        off = end;
    }
    g_num_tiles = t;
}

// -------------------- scatter: group copies by expert ---------------------
__global__ void scatter_kernel(const int* __restrict__ ei) {
    int t = blockIdx.x * blockDim.x + threadIdx.x;
    if (t < NT) {
        int e = ei[t];
        int p = atomicAdd(&g_counter[e], 1);
        g_perm[p] = t;
        g_slot[t] = p;
    }
}

// -------------------- GEMM1: gathered x @ (W1,W3) + SwiGLU ----------------
// grid: (MAX_TILES, HDIM/BN), block 256 threads, 4x4 thread tile, dual acc.
__global__ void __launch_bounds__(256)
gemm1_kernel(const float* __restrict__ x,
             const float* __restrict__ w1,
             const float* __restrict__ w3) {
    __shared__ float As[BK][BM];
    __shared__ float B1s[BK][BN];
    __shared__ float B3s[BK][BN];
    __shared__ int   srow[BM];

    int tile = blockIdx.x;
    if (tile >= g_num_tiles) return;
    const int e    = g_tile_e[tile];
    const int row0 = g_tile_row[tile];
    const int rend = g_tile_end[tile];
    const int n0   = blockIdx.y * BN;

    const int tid = threadIdx.x;
    const int tx = tid & 15;    // n-direction
    const int ty = tid >> 4;    // m-direction

    if (tid < BM) {
        int p = row0 + tid;
        if (p >= rend) p = row0;          // safe duplicate for padding rows
        srow[tid] = g_perm[p] / TOPK;     // source token
    }
    __syncthreads();

    const float* w1e = w1 + (size_t)e * DDIM * HDIM;
    const float* w3e = w3 + (size_t)e * DDIM * HDIM;

    float acc1[4][4] = {};
    float acc3[4][4] = {};

    const int lm = tid >> 2, lkq = tid & 3;    // A-load mapping
    const int lk = tid >> 4, lnq = tid & 15;   // B-load mapping

    for (int k0 = 0; k0 < DDIM; k0 += BK) {
        // load A tile (gathered rows of x), transposed into As[k][m]
        {
            float4 av = *(const float4*)(x + (size_t)srow[lm] * DDIM + k0 + lkq * 4);
            As[lkq * 4 + 0][lm] = av.x;
            As[lkq * 4 + 1][lm] = av.y;
            As[lkq * 4 + 2][lm] = av.z;
            As[lkq * 4 + 3][lm] = av.w;
        }
        // load B tiles (w1, w3 are [D][H] row-major per expert)
        {
            const float4 b1v = *(const float4*)(w1e + (size_t)(k0 + lk) * HDIM + n0 + lnq * 4);
            *(float4*)&B1s[lk][lnq * 4] = b1v;
            const float4 b3v = *(const float4*)(w3e + (size_t)(k0 + lk) * HDIM + n0 + lnq * 4);
            *(float4*)&B3s[lk][lnq * 4] = b3v;
        }
        __syncthreads();
        #pragma unroll
        for (int kk = 0; kk < BK; kk++) {
            float a[4], b1[4], b3[4];
            *(float4*)a  = *(const float4*)&As[kk][ty * 4];
            *(float4*)b1 = *(const float4*)&B1s[kk][tx * 4];
            *(float4*)b3 = *(const float4*)&B3s[kk][tx * 4];
            #pragma unroll
            for (int i = 0; i < 4; i++)
                #pragma unroll
                for (int j = 0; j < 4; j++) {
                    acc1[i][j] += a[i] * b1[j];
                    acc3[i][j] += a[i] * b3[j];
                }
        }
        __syncthreads();
    }

    // epilogue: SwiGLU, write hidden
    #pragma unroll
    for (int i = 0; i < 4; i++) {
        int row = row0 + ty * 4 + i;
        if (row < rend) {
            float4 gv;
            float* gp = (float*)&gv;
            #pragma unroll
            for (int j = 0; j < 4; j++) {
                float c1 = acc1[i][j];
                float c3 = acc3[i][j];
                float s  = c1 / (1.0f + expf(-c1));   // silu
                gp[j] = s * c3;
            }
            *(float4*)(g_hidden + (size_t)row * HDIM + n0 + tx * 4) = gv;
        }
    }
}

// -------------------- GEMM2: hidden @ W2 -> out ----------------------------
__global__ void __launch_bounds__(256)
gemm2_kernel(const float* __restrict__ w2) {
    __shared__ float As[BK][BM];
    __shared__ float Bs[BK][BN];

    int tile = blockIdx.x;
    if (tile >= g_num_tiles) return;
    const int e    = g_tile_e[tile];
    const int row0 = g_tile_row[tile];
    const int rend = g_tile_end[tile];
    const int n0   = blockIdx.y * BN;

    const int tid = threadIdx.x;
    const int tx = tid & 15;
    const int ty = tid >> 4;

    const float* w2e = w2 + (size_t)e * HDIM * DDIM;

    float acc[4][4] = {};

    const int lm = tid >> 2, lkq = tid & 3;
    const int lk = tid >> 4, lnq = tid & 15;
    int arow = row0 + lm;
    if (arow >= rend) arow = row0;

    for (int k0 = 0; k0 < HDIM; k0 += BK) {
        {
            float4 av = *(const float4*)(g_hidden + (size_t)arow * HDIM + k0 + lkq * 4);
            As[lkq * 4 + 0][lm] = av.x;
            As[lkq * 4 + 1][lm] = av.y;
            As[lkq * 4 + 2][lm] = av.z;
            As[lkq * 4 + 3][lm] = av.w;
        }
        {
            const float4 bv = *(const float4*)(w2e + (size_t)(k0 + lk) * DDIM + n0 + lnq * 4);
            *(float4*)&Bs[lk][lnq * 4] = bv;
        }
        __syncthreads();
        #pragma unroll
        for (int kk = 0; kk < BK; kk++) {
            float a[4], b[4];
            *(float4*)a = *(const float4*)&As[kk][ty * 4];
            *(float4*)b = *(const float4*)&Bs[kk][tx * 4];
            #pragma unroll
            for (int i = 0; i < 4; i++)
                #pragma unroll
                for (int j = 0; j < 4; j++)
                    acc[i][j] += a[i] * b[j];
        }
        __syncthreads();
    }

    #pragma unroll
    for (int i = 0; i < 4; i++) {
        int row = row0 + ty * 4 + i;
        if (row < rend) {
            float4 ov;
            float* op = (float*)&ov;
            #pragma unroll
            for (int j = 0; j < 4; j++) op[j] = acc[i][j];
            *(float4*)(g_out + (size_t)row * DDIM + n0 + tx * 4) = ov;
        }
    }
}

// -------------------- combine: weighted sum of K copies -------------------
__global__ void combine_kernel(const float* __restrict__ ew,
                               float* __restrict__ y) {
    int i = blockIdx.x * blockDim.x + threadIdx.x;   // over N*D/4
    const int DQ = DDIM / 4;
    int n  = i / DQ;
    int dq = i % DQ;
    int s0 = g_slot[n * TOPK + 0];
    int s1 = g_slot[n * TOPK + 1];
    float w0 = ew[n * TOPK + 0];
    float w1 = ew[n * TOPK + 1];
    float4 a = *(const float4*)(g_out + (size_t)s0 * DDIM + dq * 4);
    float4 b = *(const float4*)(g_out + (size_t)s1 * DDIM + dq * 4);
    float4 r;
    r.x = w0 * a.x + w1 * b.x;
    r.y = w0 * a.y + w1 * b.y;
    r.z = w0 * a.z + w1 * b.z;
    r.w = w0 * a.w + w1 * b.w;
    ((float4*)y)[i] = r;
}

// ---------------------------------------------------------------------------
extern "C" void kernel_launch(void* const* d_in, const int* in_sizes, int n_in,
                              void* d_out, int out_size) {
    const float* x    = (const float*)d_in[0];   // (N, D)
    const float* ew   = (const float*)d_in[1];   // (N, K)
    const float* w1   = (const float*)d_in[2];   // (E, D, H)
    const float* w2   = (const float*)d_in[3];   // (E, H, D)
    const float* w3   = (const float*)d_in[4];   // (E, D, H)
    const int*   ei   = (const int*)d_in[5];     // (N, K)
    const int*   bspe = (const int*)d_in[6];     // (E,)
    float* y = (float*)d_out;

    setup_kernel<<<1, 32>>>(bspe);
    scatter_kernel<<<NT / 256, 256>>>(ei);

    dim3 grid1(MAX_TILES, HDIM / BN);
    gemm1_kernel<<<grid1, 256>>>(x, w1, w3);

    dim3 grid2(MAX_TILES, DDIM / BN);
    gemm2_kernel<<<grid2, 256>>>(w2);

    combine_kernel<<<(N_TOK * DDIM / 4) / 256, 256>>>(ew, y);
}

// round 4
// speedup vs baseline: 3.2619x; 3.2619x over previous
#include <cuda_runtime.h>
#include <cuda_bf16.h>
#include <math.h>
#include <stdint.h>

// ---------------- problem constants ----------------
#define N_TOK 8192
#define DDIM  2048
#define HDIM  2048
#define NEXP  8
#define TOPK  2
#define NT    (N_TOK * TOPK)          // 16384 token-copies

#define BM 128
#define BN 128
#define BK 64                          // bf16 elems per stage (128 bytes/row)
#define NCH (DDIM / BK)                // 32 k-stages
#define MAX_TILES (NT / BM + NEXP)     // 136

#define TILE_B   16384                 // one 128x64 bf16 tile (128 rows x 128B)
#define STAGE_B  (4 * TILE_B)          // Ahi, Alo, Bhi, Blo
#define SMEM_REQ (2 * STAGE_B + 1024)

// ---------------- device scratch ----------------
__device__ __nv_bfloat16 g_xhi[(size_t)NT * DDIM];
__device__ __nv_bfloat16 g_xlo[(size_t)NT * DDIM];
__device__ __nv_bfloat16 g_hhi[(size_t)NT * HDIM];
__device__ __nv_bfloat16 g_hlo[(size_t)NT * HDIM];
__device__ float         g_u  [(size_t)NT * HDIM];
__device__ __nv_bfloat16 g_w1hi[(size_t)NEXP * DDIM * HDIM];  // [e][h][d]
__device__ __nv_bfloat16 g_w1lo[(size_t)NEXP * DDIM * HDIM];
__device__ __nv_bfloat16 g_w3hi[(size_t)NEXP * DDIM * HDIM];  // [e][h][d]
__device__ __nv_bfloat16 g_w3lo[(size_t)NEXP * DDIM * HDIM];
__device__ __nv_bfloat16 g_w2hi[(size_t)NEXP * HDIM * DDIM];  // [e][d][h]
__device__ __nv_bfloat16 g_w2lo[(size_t)NEXP * HDIM * DDIM];
__device__ float g_out[(size_t)NT * DDIM];

__device__ int g_perm[NT];
__device__ int g_slot[NT];
__device__ int g_counter[NEXP];
__device__ int g_tile_e[MAX_TILES];
__device__ int g_tile_row[MAX_TILES];
__device__ int g_tile_end[MAX_TILES];
__device__ int g_num_tiles;

// ---------------- helpers ----------------
__device__ __forceinline__ uint32_t cvta_smem(const void* p) {
    uint32_t a;
    asm("{ .reg .u64 t; cvta.to.shared.u64 t, %1; cvt.u32.u64 %0, t; }" : "=r"(a) : "l"(p));
    return a;
}
static __device__ __forceinline__ uint32_t swz(uint32_t b) { return b ^ ((b >> 3) & 0x70); }

__device__ __forceinline__ void cp16(uint32_t dst, const void* src) {
    asm volatile("cp.async.cg.shared.global [%0], [%1], 16;" :: "r"(dst), "l"(src));
}
__device__ __forceinline__ void cp_commit() {
    asm volatile("cp.async.commit_group;" ::: "memory");
}
__device__ __forceinline__ void ldm_x4(uint32_t* r, uint32_t addr) {
    asm volatile("ldmatrix.sync.aligned.m8n8.x4.shared.b16 {%0,%1,%2,%3}, [%4];"
                 : "=r"(r[0]), "=r"(r[1]), "=r"(r[2]), "=r"(r[3]) : "r"(addr));
}
__device__ __forceinline__ void mma16816(float* d, const uint32_t* a, const uint32_t* b) {
    asm volatile(
        "mma.sync.aligned.m16n8k16.row.col.f32.bf16.bf16.f32 "
        "{%0,%1,%2,%3}, {%4,%5,%6,%7}, {%8,%9}, {%0,%1,%2,%3};"
        : "+f"(d[0]), "+f"(d[1]), "+f"(d[2]), "+f"(d[3])
        : "r"(a[0]), "r"(a[1]), "r"(a[2]), "r"(a[3]), "r"(b[0]), "r"(b[1]));
}
__device__ __forceinline__ void split_bf16(float v, __nv_bfloat16& hi, __nv_bfloat16& lo) {
    hi = __float2bfloat16(v);
    lo = __float2bfloat16(v - __bfloat162float(hi));
}

// ---------------- setup / scatter / converts ----------------
__global__ void setup_kernel(const int* __restrict__ bspe) {
    if (threadIdx.x != 0 || blockIdx.x != 0) return;
    int off = 0, t = 0;
    for (int e = 0; e < NEXP; e++) {
        int c = bspe[e];
        g_counter[e] = off;
        int end = off + c;
        for (int r = off; r < end; r += BM) {
            g_tile_e[t] = e; g_tile_row[t] = r; g_tile_end[t] = end; t++;
        }
        off = end;
    }
    g_num_tiles = t;
}

__global__ void scatter_kernel(const int* __restrict__ ei) {
    int t = blockIdx.x * blockDim.x + threadIdx.x;
    if (t < NT) {
        int e = ei[t];
        int p = atomicAdd(&g_counter[e], 1);
        g_perm[p] = t;
        g_slot[t] = p;
    }
}

__global__ void convert_x_kernel(const float* __restrict__ x) {
    int idx = blockIdx.x * 256 + threadIdx.x;
    int p  = idx / (DDIM / 4);
    int c4 = (idx % (DDIM / 4)) * 4;
    int tok = g_perm[p] / TOPK;
    float4 v = *(const float4*)(x + (size_t)tok * DDIM + c4);
    __nv_bfloat162 h0, h1, l0, l1;
    split_bf16(v.x, h0.x, l0.x); split_bf16(v.y, h0.y, l0.y);
    split_bf16(v.z, h1.x, l1.x); split_bf16(v.w, h1.y, l1.y);
    size_t o = (size_t)p * DDIM + c4;
    *(__nv_bfloat162*)(g_xhi + o)     = h0;
    *(__nv_bfloat162*)(g_xhi + o + 2) = h1;
    *(__nv_bfloat162*)(g_xlo + o)     = l0;
    *(__nv_bfloat162*)(g_xlo + o + 2) = l1;
}

// src [E][K][N] fp32 -> dst [E][N][K] bf16 hi/lo  (B^T, k contiguous)
// W selects the destination device-globals IN DEVICE CODE (host must never
// take the address of a __device__ global — that was the Round-3 bug).
template <int W>
__global__ void convert_w_kernel(const float* __restrict__ src) {
    __nv_bfloat16* dhi = (W == 0) ? g_w1hi : (W == 1) ? g_w3hi : g_w2hi;
    __nv_bfloat16* dlo = (W == 0) ? g_w1lo : (W == 1) ? g_w3lo : g_w2lo;
    __shared__ float s[64][65];
    int e  = blockIdx.z;
    int k0 = blockIdx.x * 64;
    int n0 = blockIdx.y * 64;
    const float* se = src + (size_t)e * 2048 * 2048;
    int tr = threadIdx.x >> 4;
    int tc = (threadIdx.x & 15) * 4;
    #pragma unroll
    for (int i = 0; i < 4; i++) {
        int kl = tr + i * 16;
        float4 v = *(const float4*)(se + (size_t)(k0 + kl) * 2048 + n0 + tc);
        s[kl][tc + 0] = v.x; s[kl][tc + 1] = v.y; s[kl][tc + 2] = v.z; s[kl][tc + 3] = v.w;
    }
    __syncthreads();
    #pragma unroll
    for (int i = 0; i < 4; i++) {
        int nl = tr + i * 16;
        size_t o = ((size_t)e * 2048 + n0 + nl) * 2048 + k0 + tc;
        __nv_bfloat162 h0, h1, l0, l1;
        split_bf16(s[tc + 0][nl], h0.x, l0.x);
        split_bf16(s[tc + 1][nl], h0.y, l0.y);
        split_bf16(s[tc + 2][nl], h1.x, l1.x);
        split_bf16(s[tc + 3][nl], h1.y, l1.y);
        *(__nv_bfloat162*)(dhi + o)     = h0;
        *(__nv_bfloat162*)(dhi + o + 2) = h1;
        *(__nv_bfloat162*)(dlo + o)     = l0;
        *(__nv_bfloat162*)(dlo + o + 2) = l1;
    }
}

// ---------------- unified mma.sync GEMM ----------------
// MODE 0: u = x @ w3              -> g_u (fp32)
// MODE 1: g = x @ w1, h=silu(g)*u -> g_hhi/g_hlo (bf16 split)
// MODE 2: o = h @ w2              -> g_out (fp32)
template <int MODE>
__global__ void __launch_bounds__(256, 1) gemm_kernel() {
    int tile = blockIdx.y;
    if (tile >= g_num_tiles) return;
    const int e    = g_tile_e[tile];
    const int row0 = g_tile_row[tile];
    const int rend = g_tile_end[tile];
    const int n0   = blockIdx.x * BN;

    const __nv_bfloat16* Ahi = (MODE < 2) ? g_xhi : g_hhi;
    const __nv_bfloat16* Alo = (MODE < 2) ? g_xlo : g_hlo;
    const __nv_bfloat16* Bhi;
    const __nv_bfloat16* Blo;
    if (MODE == 0)      { Bhi = g_w3hi + (size_t)e * DDIM * HDIM; Blo = g_w3lo + (size_t)e * DDIM * HDIM; }
    else if (MODE == 1) { Bhi = g_w1hi + (size_t)e * DDIM * HDIM; Blo = g_w1lo + (size_t)e * DDIM * HDIM; }
    else                { Bhi = g_w2hi + (size_t)e * HDIM * DDIM; Blo = g_w2lo + (size_t)e * HDIM * DDIM; }

    extern __shared__ char smem[];
    uint32_t sbase = (cvta_smem(smem) + 1023) & ~1023u;

    const int tid  = threadIdx.x;
    const int wid  = tid >> 5;
    const int lane = tid & 31;
    const int wm   = wid & 1;          // 2 warp-rows  (64 rows each)
    const int wn   = wid >> 1;         // 4 warp-cols  (32 cols each)

    auto load_stage = [&](int c) {
        uint32_t st = sbase + (uint32_t)(c & 1) * STAGE_B;
        int kel = c * BK;
        #pragma unroll
        for (int it = 0; it < 4; it++) {
            int chunk = it * 256 + tid;
            int row = chunk >> 3;
            int kb  = (chunk & 7) * 16;
            uint32_t so = swz((uint32_t)(row * 128 + kb));
            int ra = row0 + row; if (ra > NT - 1) ra = NT - 1;
            size_t ga = (size_t)ra * 2048 + kel + kb / 2;
            size_t gb = (size_t)(n0 + row) * 2048 + kel + kb / 2;
            cp16(st + 0 * TILE_B + so, Ahi + ga);
            cp16(st + 1 * TILE_B + so, Alo + ga);
            cp16(st + 2 * TILE_B + so, Bhi + gb);
            cp16(st + 3 * TILE_B + so, Blo + gb);
        }
        cp_commit();
    };

    float acc[4][4][4] = {};

    const int aRow = lane & 15;
    const int aKof = (lane >> 4) * 16;
    const int bRow = (lane & 7) + ((lane >> 4) & 1) * 8;
    const int bKof = ((lane >> 3) & 1) * 16;

    load_stage(0);
    for (int c = 0; c < NCH; c++) {
        if (c + 1 < NCH) {
            load_stage(c + 1);
            asm volatile("cp.async.wait_group 1;" ::: "memory");
        } else {
            asm volatile("cp.async.wait_group 0;" ::: "memory");
        }
        __syncthreads();

        uint32_t st = sbase + (uint32_t)(c & 1) * STAGE_B;
        #pragma unroll
        for (int ks = 0; ks < 4; ks++) {
            int kb = ks * 32;
            uint32_t ah[4][4], al[4][4], bh[4][2], bl[4][2];
            #pragma unroll
            for (int mi = 0; mi < 4; mi++) {
                int r = wm * 64 + mi * 16 + aRow;
                uint32_t off = swz((uint32_t)(r * 128 + kb + aKof));
                ldm_x4(ah[mi], st + 0 * TILE_B + off);
                ldm_x4(al[mi], st + 1 * TILE_B + off);
            }
            #pragma unroll
            for (int p = 0; p < 2; p++) {
                int r = wn * 32 + p * 16 + bRow;
                uint32_t off = swz((uint32_t)(r * 128 + kb + bKof));
                uint32_t t4[4];
                ldm_x4(t4, st + 2 * TILE_B + off);
                bh[2*p][0] = t4[0]; bh[2*p][1] = t4[1];
                bh[2*p+1][0] = t4[2]; bh[2*p+1][1] = t4[3];
                ldm_x4(t4, st + 3 * TILE_B + off);
                bl[2*p][0] = t4[0]; bl[2*p][1] = t4[1];
                bl[2*p+1][0] = t4[2]; bl[2*p+1][1] = t4[3];
            }
            #pragma unroll
            for (int mi = 0; mi < 4; mi++)
                #pragma unroll
                for (int ni = 0; ni < 4; ni++) {
                    mma16816(acc[mi][ni], ah[mi], bh[ni]);
                    mma16816(acc[mi][ni], ah[mi], bl[ni]);
                    mma16816(acc[mi][ni], al[mi], bh[ni]);
                }
        }
        __syncthreads();
    }

    const int erow = lane >> 2;
    const int ecol = (lane & 3) * 2;
    #pragma unroll
    for (int mi = 0; mi < 4; mi++) {
        #pragma unroll
        for (int ni = 0; ni < 4; ni++) {
            int gr0 = row0 + wm * 64 + mi * 16 + erow;
            int gc  = n0 + wn * 32 + ni * 8 + ecol;
            #pragma unroll
            for (int h = 0; h < 2; h++) {
                int gr = gr0 + h * 8;
                if (gr >= rend) continue;
                float v0 = acc[mi][ni][h * 2 + 0];
                float v1 = acc[mi][ni][h * 2 + 1];
                size_t o = (size_t)gr * 2048 + gc;
                if (MODE == 0) {
                    *(float2*)(g_u + o) = make_float2(v0, v1);
                } else if (MODE == 1) {
                    float2 u = *(const float2*)(g_u + o);
                    float h0 = v0 / (1.0f + __expf(-v0)) * u.x;
                    float h1 = v1 / (1.0f + __expf(-v1)) * u.y;
                    __nv_bfloat162 ph, pl;
                    split_bf16(h0, ph.x, pl.x);
                    split_bf16(h1, ph.y, pl.y);
                    *(__nv_bfloat162*)(g_hhi + o) = ph;
                    *(__nv_bfloat162*)(g_hlo + o) = pl;
                } else {
                    *(float2*)(g_out + o) = make_float2(v0, v1);
                }
            }
        }
    }
}

// ---------------- combine ----------------
__global__ void combine_kernel(const float* __restrict__ ew, float* __restrict__ y) {
    int i = blockIdx.x * blockDim.x + threadIdx.x;
    const int DQ = DDIM / 4;
    int n  = i / DQ;
    int dq = i % DQ;
    int s0 = g_slot[n * TOPK + 0];
    int s1 = g_slot[n * TOPK + 1];
    float w0 = ew[n * TOPK + 0];
    float w1 = ew[n * TOPK + 1];
    float4 a = *(const float4*)(g_out + (size_t)s0 * DDIM + dq * 4);
    float4 b = *(const float4*)(g_out + (size_t)s1 * DDIM + dq * 4);
    float4 r;
    r.x = w0 * a.x + w1 * b.x;
    r.y = w0 * a.y + w1 * b.y;
    r.z = w0 * a.z + w1 * b.z;
    r.w = w0 * a.w + w1 * b.w;
    ((float4*)y)[i] = r;
}

// ---------------------------------------------------------------------------
extern "C" void kernel_launch(void* const* d_in, const int* in_sizes, int n_in,
                              void* d_out, int out_size) {
    const float* x    = (const float*)d_in[0];
    const float* ew   = (const float*)d_in[1];
    const float* w1   = (const float*)d_in[2];
    const float* w2   = (const float*)d_in[3];
    const float* w3   = (const float*)d_in[4];
    const int*   ei   = (const int*)d_in[5];
    const int*   bspe = (const int*)d_in[6];
    float* y = (float*)d_out;

    cudaFuncSetAttribute(gemm_kernel<0>, cudaFuncAttributeMaxDynamicSharedMemorySize, SMEM_REQ);
    cudaFuncSetAttribute(gemm_kernel<1>, cudaFuncAttributeMaxDynamicSharedMemorySize, SMEM_REQ);
    cudaFuncSetAttribute(gemm_kernel<2>, cudaFuncAttributeMaxDynamicSharedMemorySize, SMEM_REQ);

    setup_kernel<<<1, 32>>>(bspe);
    scatter_kernel<<<NT / 256, 256>>>(ei);
    convert_x_kernel<<<(NT * DDIM / 4) / 256, 256>>>(x);

    dim3 wgrid(32, 32, NEXP);
    convert_w_kernel<0><<<wgrid, 256>>>(w1);
    convert_w_kernel<1><<<wgrid, 256>>>(w3);
    convert_w_kernel<2><<<wgrid, 256>>>(w2);

    dim3 gg(HDIM / BN, MAX_TILES);
    gemm_kernel<0><<<gg, 256, SMEM_REQ>>>();
    gemm_kernel<1><<<gg, 256, SMEM_REQ>>>();
    dim3 g2(DDIM / BN, MAX_TILES);
    gemm_kernel<2><<<g2, 256, SMEM_REQ>>>();

    combine_kernel<<<(N_TOK * DDIM / 4) / 256, 256>>>(ew, y);
}

// round 5
// speedup vs baseline: 3.5995x; 1.1035x over previous
#include <cuda_runtime.h>
#include <cuda_bf16.h>
#include <math.h>
#include <stdint.h>

// ---------------- problem constants ----------------
#define N_TOK 8192
#define DDIM  2048
#define HDIM  2048
#define NEXP  8
#define TOPK  2
#define NT    (N_TOK * TOPK)          // 16384 token-copies

#define BM 128
#define BK 64                          // bf16 elems per stage (128 bytes/row)
#define NCH (DDIM / BK)                // 32 k-stages
#define MAX_TILES (NT / BM + NEXP)     // 136

#define TILE_A   16384                 // 128 rows x 128B
#define TILE_B2  32768                 // 256 rows x 128B
#define STAGE1_B (6 * TILE_A)          // Ahi,Alo,B1hi,B1lo,B3hi,B3lo  (96KB)
#define STAGE2_B (2 * TILE_A + 2 * TILE_B2)  // Ahi,Alo,Bhi,Blo        (96KB)
#define SMEM_REQ (2 * STAGE1_B + 1024) // 193KB (same for both gemms)

// ---------------- device scratch ----------------
__device__ __nv_bfloat16 g_xhi[(size_t)NT * DDIM];
__device__ __nv_bfloat16 g_xlo[(size_t)NT * DDIM];
__device__ __nv_bfloat16 g_hhi[(size_t)NT * HDIM];
__device__ __nv_bfloat16 g_hlo[(size_t)NT * HDIM];
__device__ __nv_bfloat16 g_w1hi[(size_t)NEXP * DDIM * HDIM];  // [e][h][d]
__device__ __nv_bfloat16 g_w1lo[(size_t)NEXP * DDIM * HDIM];
__device__ __nv_bfloat16 g_w3hi[(size_t)NEXP * DDIM * HDIM];  // [e][h][d]
__device__ __nv_bfloat16 g_w3lo[(size_t)NEXP * DDIM * HDIM];
__device__ __nv_bfloat16 g_w2hi[(size_t)NEXP * HDIM * DDIM];  // [e][d][h]
__device__ __nv_bfloat16 g_w2lo[(size_t)NEXP * HDIM * DDIM];
__device__ float g_out[(size_t)NT * DDIM];

__device__ int g_perm[NT];
__device__ int g_slot[NT];
__device__ int g_counter[NEXP];
__device__ int g_tile_e[MAX_TILES];
__device__ int g_tile_row[MAX_TILES];
__device__ int g_tile_end[MAX_TILES];
__device__ int g_num_tiles;

// ---------------- helpers ----------------
__device__ __forceinline__ uint32_t cvta_smem(const void* p) {
    uint32_t a;
    asm("{ .reg .u64 t; cvta.to.shared.u64 t, %1; cvt.u32.u64 %0, t; }" : "=r"(a) : "l"(p));
    return a;
}
static __device__ __forceinline__ uint32_t swz(uint32_t b) { return b ^ ((b >> 3) & 0x70); }

__device__ __forceinline__ void cp16(uint32_t dst, const void* src) {
    asm volatile("cp.async.cg.shared.global [%0], [%1], 16;" :: "r"(dst), "l"(src));
}
__device__ __forceinline__ void cp_commit() {
    asm volatile("cp.async.commit_group;" ::: "memory");
}
__device__ __forceinline__ void ldm_x4(uint32_t* r, uint32_t addr) {
    asm volatile("ldmatrix.sync.aligned.m8n8.x4.shared.b16 {%0,%1,%2,%3}, [%4];"
                 : "=r"(r[0]), "=r"(r[1]), "=r"(r[2]), "=r"(r[3]) : "r"(addr));
}
__device__ __forceinline__ void mma16816(float* d, const uint32_t* a, const uint32_t* b) {
    asm volatile(
        "mma.sync.aligned.m16n8k16.row.col.f32.bf16.bf16.f32 "
        "{%0,%1,%2,%3}, {%4,%5,%6,%7}, {%8,%9}, {%0,%1,%2,%3};"
        : "+f"(d[0]), "+f"(d[1]), "+f"(d[2]), "+f"(d[3])
        : "r"(a[0]), "r"(a[1]), "r"(a[2]), "r"(a[3]), "r"(b[0]), "r"(b[1]));
}
__device__ __forceinline__ void split_bf16(float v, __nv_bfloat16& hi, __nv_bfloat16& lo) {
    hi = __float2bfloat16(v);
    lo = __float2bfloat16(v - __bfloat162float(hi));
}

// ---------------- setup / scatter / converts ----------------
__global__ void setup_kernel(const int* __restrict__ bspe) {
    if (threadIdx.x != 0 || blockIdx.x != 0) return;
    int off = 0, t = 0;
    for (int e = 0; e < NEXP; e++) {
        int c = bspe[e];
        g_counter[e] = off;
        int end = off + c;
        for (int r = off; r < end; r += BM) {
            g_tile_e[t] = e; g_tile_row[t] = r; g_tile_end[t] = end; t++;
        }
        off = end;
    }
    g_num_tiles = t;
}

__global__ void scatter_kernel(const int* __restrict__ ei) {
    int t = blockIdx.x * blockDim.x + threadIdx.x;
    if (t < NT) {
        int e = ei[t];
        int p = atomicAdd(&g_counter[e], 1);
        g_perm[p] = t;
        g_slot[t] = p;
    }
}

__global__ void convert_x_kernel(const float* __restrict__ x) {
    int idx = blockIdx.x * 256 + threadIdx.x;
    int p  = idx / (DDIM / 4);
    int c4 = (idx % (DDIM / 4)) * 4;
    int tok = g_perm[p] / TOPK;
    float4 v = *(const float4*)(x + (size_t)tok * DDIM + c4);
    __nv_bfloat162 h0, h1, l0, l1;
    split_bf16(v.x, h0.x, l0.x); split_bf16(v.y, h0.y, l0.y);
    split_bf16(v.z, h1.x, l1.x); split_bf16(v.w, h1.y, l1.y);
    size_t o = (size_t)p * DDIM + c4;
    *(__nv_bfloat162*)(g_xhi + o)     = h0;
    *(__nv_bfloat162*)(g_xhi + o + 2) = h1;
    *(__nv_bfloat162*)(g_xlo + o)     = l0;
    *(__nv_bfloat162*)(g_xlo + o + 2) = l1;
}

// src [E][K][N] fp32 -> dst [E][N][K] bf16 hi/lo; W selects dst inside device code
template <int W>
__global__ void convert_w_kernel(const float* __restrict__ src) {
    __nv_bfloat16* dhi = (W == 0) ? g_w1hi : (W == 1) ? g_w3hi : g_w2hi;
    __nv_bfloat16* dlo = (W == 0) ? g_w1lo : (W == 1) ? g_w3lo : g_w2lo;
    __shared__ float s[64][65];
    int e  = blockIdx.z;
    int k0 = blockIdx.x * 64;
    int n0 = blockIdx.y * 64;
    const float* se = src + (size_t)e * 2048 * 2048;
    int tr = threadIdx.x >> 4;
    int tc = (threadIdx.x & 15) * 4;
    #pragma unroll
    for (int i = 0; i < 4; i++) {
        int kl = tr + i * 16;
        float4 v = *(const float4*)(se + (size_t)(k0 + kl) * 2048 + n0 + tc);
        s[kl][tc + 0] = v.x; s[kl][tc + 1] = v.y; s[kl][tc + 2] = v.z; s[kl][tc + 3] = v.w;
    }
    __syncthreads();
    #pragma unroll
    for (int i = 0; i < 4; i++) {
        int nl = tr + i * 16;
        size_t o = ((size_t)e * 2048 + n0 + nl) * 2048 + k0 + tc;
        __nv_bfloat162 h0, h1, l0, l1;
        split_bf16(s[tc + 0][nl], h0.x, l0.x);
        split_bf16(s[tc + 1][nl], h0.y, l0.y);
        split_bf16(s[tc + 2][nl], h1.x, l1.x);
        split_bf16(s[tc + 3][nl], h1.y, l1.y);
        *(__nv_bfloat162*)(dhi + o)     = h0;
        *(__nv_bfloat162*)(dhi + o + 2) = h1;
        *(__nv_bfloat162*)(dlo + o)     = l0;
        *(__nv_bfloat162*)(dlo + o + 2) = l1;
    }
}

// ---------------- GEMM1 (merged): g = x@w1, u = x@w3, h = silu(g)*u ----------
// CTA 128x128, 8 warps as 2(m)x4(n), warp tile 64x32, dual accumulators.
__global__ void __launch_bounds__(256, 1) gemm1_kernel() {
    int tile = blockIdx.y;
    if (tile >= g_num_tiles) return;
    const int e    = g_tile_e[tile];
    const int row0 = g_tile_row[tile];
    const int rend = g_tile_end[tile];
    const int n0   = blockIdx.x * 128;

    const __nv_bfloat16* B1h = g_w1hi + (size_t)e * DDIM * HDIM;
    const __nv_bfloat16* B1l = g_w1lo + (size_t)e * DDIM * HDIM;
    const __nv_bfloat16* B3h = g_w3hi + (size_t)e * DDIM * HDIM;
    const __nv_bfloat16* B3l = g_w3lo + (size_t)e * DDIM * HDIM;

    extern __shared__ char smem[];
    uint32_t sbase = (cvta_smem(smem) + 1023) & ~1023u;

    const int tid  = threadIdx.x;
    const int wid  = tid >> 5;
    const int lane = tid & 31;
    const int wm   = wid & 1;
    const int wn   = wid >> 1;

    auto load_stage = [&](int c) {
        uint32_t st = sbase + (uint32_t)(c & 1) * STAGE1_B;
        int kel = c * BK;
        #pragma unroll
        for (int it = 0; it < 4; it++) {
            int chunk = it * 256 + tid;          // 0..1023
            int row = chunk >> 3;
            int kb  = (chunk & 7) * 16;
            uint32_t so = swz((uint32_t)(row * 128 + kb));
            int ra = row0 + row; if (ra > NT - 1) ra = NT - 1;
            size_t ga = (size_t)ra * 2048 + kel + kb / 2;
            size_t gb = (size_t)(n0 + row) * 2048 + kel + kb / 2;
            cp16(st + 0 * TILE_A + so, g_xhi + ga);
            cp16(st + 1 * TILE_A + so, g_xlo + ga);
            cp16(st + 2 * TILE_A + so, B1h + gb);
            cp16(st + 3 * TILE_A + so, B1l + gb);
            cp16(st + 4 * TILE_A + so, B3h + gb);
            cp16(st + 5 * TILE_A + so, B3l + gb);
        }
        cp_commit();
    };

    float acc1[4][4][4] = {};
    float acc3[4][4][4] = {};

    const int aRow = lane & 15;
    const int aKof = (lane >> 4) * 16;
    const int bRow = (lane & 7) + ((lane >> 4) & 1) * 8;
    const int bKof = ((lane >> 3) & 1) * 16;

    load_stage(0);
    for (int c = 0; c < NCH; c++) {
        if (c + 1 < NCH) {
            load_stage(c + 1);
            asm volatile("cp.async.wait_group 1;" ::: "memory");
        } else {
            asm volatile("cp.async.wait_group 0;" ::: "memory");
        }
        __syncthreads();

        uint32_t st = sbase + (uint32_t)(c & 1) * STAGE1_B;
        #pragma unroll
        for (int ks = 0; ks < 4; ks++) {
            int kb = ks * 32;
            uint32_t ah[4][4], al[4][4];
            #pragma unroll
            for (int mi = 0; mi < 4; mi++) {
                int r = wm * 64 + mi * 16 + aRow;
                uint32_t off = swz((uint32_t)(r * 128 + kb + aKof));
                ldm_x4(ah[mi], st + 0 * TILE_A + off);
                ldm_x4(al[mi], st + 1 * TILE_A + off);
            }
            #pragma unroll
            for (int p = 0; p < 2; p++) {
                int r = wn * 32 + p * 16 + bRow;
                uint32_t off = swz((uint32_t)(r * 128 + kb + bKof));
                // ---- w1 ----
                uint32_t th[4], tl[4];
                ldm_x4(th, st + 2 * TILE_A + off);
                ldm_x4(tl, st + 3 * TILE_A + off);
                #pragma unroll
                for (int q = 0; q < 2; q++) {
                    uint32_t bh2[2] = { th[2*q], th[2*q+1] };
                    uint32_t bl2[2] = { tl[2*q], tl[2*q+1] };
                    int ni = 2 * p + q;
                    #pragma unroll
                    for (int mi = 0; mi < 4; mi++) {
                        mma16816(acc1[mi][ni], ah[mi], bh2);
                        mma16816(acc1[mi][ni], ah[mi], bl2);
                        mma16816(acc1[mi][ni], al[mi], bh2);
                    }
                }
                // ---- w3 ----
                ldm_x4(th, st + 4 * TILE_A + off);
                ldm_x4(tl, st + 5 * TILE_A + off);
                #pragma unroll
                for (int q = 0; q < 2; q++) {
                    uint32_t bh2[2] = { th[2*q], th[2*q+1] };
                    uint32_t bl2[2] = { tl[2*q], tl[2*q+1] };
                    int ni = 2 * p + q;
                    #pragma unroll
                    for (int mi = 0; mi < 4; mi++) {
                        mma16816(acc3[mi][ni], ah[mi], bh2);
                        mma16816(acc3[mi][ni], ah[mi], bl2);
                        mma16816(acc3[mi][ni], al[mi], bh2);
                    }
                }
            }
        }
        __syncthreads();
    }

    // epilogue: h = silu(g) * u -> bf16 hi/lo
    const int erow = lane >> 2;
    const int ecol = (lane & 3) * 2;
    #pragma unroll
    for (int mi = 0; mi < 4; mi++) {
        #pragma unroll
        for (int ni = 0; ni < 4; ni++) {
            int gr0 = row0 + wm * 64 + mi * 16 + erow;
            int gc  = n0 + wn * 32 + ni * 8 + ecol;
            #pragma unroll
            for (int h = 0; h < 2; h++) {
                int gr = gr0 + h * 8;
                if (gr >= rend) continue;
                float gv0 = acc1[mi][ni][h * 2 + 0];
                float gv1 = acc1[mi][ni][h * 2 + 1];
                float uv0 = acc3[mi][ni][h * 2 + 0];
                float uv1 = acc3[mi][ni][h * 2 + 1];
                float h0 = gv0 / (1.0f + __expf(-gv0)) * uv0;
                float h1 = gv1 / (1.0f + __expf(-gv1)) * uv1;
                __nv_bfloat162 ph, pl;
                split_bf16(h0, ph.x, pl.x);
                split_bf16(h1, ph.y, pl.y);
                size_t o = (size_t)gr * 2048 + gc;
                *(__nv_bfloat162*)(g_hhi + o) = ph;
                *(__nv_bfloat162*)(g_hlo + o) = pl;
            }
        }
    }
}

// ---------------- GEMM2: out = h @ w2  (CTA 128x256, warp tile 64x64) -------
__global__ void __launch_bounds__(256, 1) gemm2_kernel() {
    int tile = blockIdx.y;
    if (tile >= g_num_tiles) return;
    const int e    = g_tile_e[tile];
    const int row0 = g_tile_row[tile];
    const int rend = g_tile_end[tile];
    const int n0   = blockIdx.x * 256;

    const __nv_bfloat16* Bh = g_w2hi + (size_t)e * HDIM * DDIM;
    const __nv_bfloat16* Bl = g_w2lo + (size_t)e * HDIM * DDIM;

    extern __shared__ char smem[];
    uint32_t sbase = (cvta_smem(smem) + 1023) & ~1023u;

    const int tid  = threadIdx.x;
    const int wid  = tid >> 5;
    const int lane = tid & 31;
    const int wm   = wid & 1;          // 2 warp-rows (64 rows)
    const int wn   = wid >> 1;         // 4 warp-cols (64 cols)

    // smem layout within stage: [0,16K) Ahi, [16K,32K) Alo, [32K,64K) Bhi, [64K,96K) Blo
    auto load_stage = [&](int c) {
        uint32_t st = sbase + (uint32_t)(c & 1) * STAGE2_B;
        int kel = c * BK;
        #pragma unroll
        for (int it = 0; it < 4; it++) {
            int chunk = it * 256 + tid;          // 0..1023 (A tiles)
            int row = chunk >> 3;
            int kb  = (chunk & 7) * 16;
            uint32_t so = swz((uint32_t)(row * 128 + kb));
            int ra = row0 + row; if (ra > NT - 1) ra = NT - 1;
            size_t ga = (size_t)ra * 2048 + kel + kb / 2;
            cp16(st + 0 * TILE_A + so, g_hhi + ga);
            cp16(st + 1 * TILE_A + so, g_hlo + ga);
        }
        #pragma unroll
        for (int it = 0; it < 8; it++) {
            int chunk = it * 256 + tid;          // 0..2047 (B tiles, 256 rows)
            int row = chunk >> 3;
            int kb  = (chunk & 7) * 16;
            uint32_t so = swz((uint32_t)(row * 128 + kb));
            size_t gb = (size_t)(n0 + row) * 2048 + kel + kb / 2;
            cp16(st + 2 * TILE_A + so, Bh + gb);
            cp16(st + 2 * TILE_A + TILE_B2 + so, Bl + gb);
        }
        cp_commit();
    };

    float acc[4][8][4] = {};

    const int aRow = lane & 15;
    const int aKof = (lane >> 4) * 16;
    const int bRow = (lane & 7) + ((lane >> 4) & 1) * 8;
    const int bKof = ((lane >> 3) & 1) * 16;

    load_stage(0);
    for (int c = 0; c < NCH; c++) {
        if (c + 1 < NCH) {
            load_stage(c + 1);
            asm volatile("cp.async.wait_group 1;" ::: "memory");
        } else {
            asm volatile("cp.async.wait_group 0;" ::: "memory");
        }
        __syncthreads();

        uint32_t st = sbase + (uint32_t)(c & 1) * STAGE2_B;
        #pragma unroll
        for (int ks = 0; ks < 4; ks++) {
            int kb = ks * 32;
            uint32_t ah[4][4], al[4][4];
            #pragma unroll
            for (int mi = 0; mi < 4; mi++) {
                int r = wm * 64 + mi * 16 + aRow;
                uint32_t off = swz((uint32_t)(r * 128 + kb + aKof));
                ldm_x4(ah[mi], st + 0 * TILE_A + off);
                ldm_x4(al[mi], st + 1 * TILE_A + off);
            }
            #pragma unroll
            for (int p = 0; p < 4; p++) {
                int r = wn * 64 + p * 16 + bRow;
                uint32_t off = swz((uint32_t)(r * 128 + kb + bKof));
                uint32_t th[4], tl[4];
                ldm_x4(th, st + 2 * TILE_A + off);
                ldm_x4(tl, st + 2 * TILE_A + TILE_B2 + off);
                #pragma unroll
                for (int q = 0; q < 2; q++) {
                    uint32_t bh2[2] = { th[2*q], th[2*q+1] };
                    uint32_t bl2[2] = { tl[2*q], tl[2*q+1] };
                    int ni = 2 * p + q;
                    #pragma unroll
                    for (int mi = 0; mi < 4; mi++) {
                        mma16816(acc[mi][ni], ah[mi], bh2);
                        mma16816(acc[mi][ni], ah[mi], bl2);
                        mma16816(acc[mi][ni], al[mi], bh2);
                    }
                }
            }
        }
        __syncthreads();
    }

    const int erow = lane >> 2;
    const int ecol = (lane & 3) * 2;
    #pragma unroll
    for (int mi = 0; mi < 4; mi++) {
        #pragma unroll
        for (int ni = 0; ni < 8; ni++) {
            int gr0 = row0 + wm * 64 + mi * 16 + erow;
            int gc  = n0 + wn * 64 + ni * 8 + ecol;
            #pragma unroll
            for (int h = 0; h < 2; h++) {
                int gr = gr0 + h * 8;
                if (gr >= rend) continue;
                size_t o = (size_t)gr * 2048 + gc;
                *(float2*)(g_out + o) =
                    make_float2(acc[mi][ni][h * 2 + 0], acc[mi][ni][h * 2 + 1]);
            }
        }
    }
}

// ---------------- combine ----------------
__global__ void combine_kernel(const float* __restrict__ ew, float* __restrict__ y) {
    int i = blockIdx.x * blockDim.x + threadIdx.x;
    const int DQ = DDIM / 4;
    int n  = i / DQ;
    int dq = i % DQ;
    int s0 = g_slot[n * TOPK + 0];
    int s1 = g_slot[n * TOPK + 1];
    float w0 = ew[n * TOPK + 0];
    float w1 = ew[n * TOPK + 1];
    float4 a = *(const float4*)(g_out + (size_t)s0 * DDIM + dq * 4);
    float4 b = *(const float4*)(g_out + (size_t)s1 * DDIM + dq * 4);
    float4 r;
    r.x = w0 * a.x + w1 * b.x;
    r.y = w0 * a.y + w1 * b.y;
    r.z = w0 * a.z + w1 * b.z;
    r.w = w0 * a.w + w1 * b.w;
    ((float4*)y)[i] = r;
}

// ---------------------------------------------------------------------------
extern "C" void kernel_launch(void* const* d_in, const int* in_sizes, int n_in,
                              void* d_out, int out_size) {
    const float* x    = (const float*)d_in[0];
    const float* ew   = (const float*)d_in[1];
    const float* w1   = (const float*)d_in[2];
    const float* w2   = (const float*)d_in[3];
    const float* w3   = (const float*)d_in[4];
    const int*   ei   = (const int*)d_in[5];
    const int*   bspe = (const int*)d_in[6];
    float* y = (float*)d_out;

    cudaFuncSetAttribute(gemm1_kernel, cudaFuncAttributeMaxDynamicSharedMemorySize, SMEM_REQ);
    cudaFuncSetAttribute(gemm2_kernel, cudaFuncAttributeMaxDynamicSharedMemorySize, SMEM_REQ);

    setup_kernel<<<1, 32>>>(bspe);
    scatter_kernel<<<NT / 256, 256>>>(ei);
    convert_x_kernel<<<(NT * DDIM / 4) / 256, 256>>>(x);

    dim3 wgrid(32, 32, NEXP);
    convert_w_kernel<0><<<wgrid, 256>>>(w1);
    convert_w_kernel<1><<<wgrid, 256>>>(w3);
    convert_w_kernel<2><<<wgrid, 256>>>(w2);

    dim3 g1(HDIM / 128, MAX_TILES);
    gemm1_kernel<<<g1, 256, SMEM_REQ>>>();
    dim3 g2(DDIM / 256, MAX_TILES);
    gemm2_kernel<<<g2, 256, SMEM_REQ>>>();

    combine_kernel<<<(N_TOK * DDIM / 4) / 256, 256>>>(ew, y);
}

// round 6
// speedup vs baseline: 4.9862x; 1.3852x over previous
#include <cuda_runtime.h>
#include <cuda_bf16.h>
#include <cuda_fp16.h>
#include <math.h>
#include <stdint.h>

// ---------------- problem constants ----------------
#define N_TOK 8192
#define DDIM  2048
#define HDIM  2048
#define NEXP  8
#define TOPK  2
#define NT    (N_TOK * TOPK)          // 16384 token-copies

#define BM 128
#define BK 64                          // fp16 elems per stage (128 bytes/row)
#define NCH (DDIM / BK)                // 32 k-stages
#define MAX_TILES (NT / BM + NEXP)     // 136

#define TILE_A   16384                 // 128 rows x 128B
#define TILE_B2  32768                 // 256 rows x 128B
#define STAGE1_B (5 * TILE_A)          // A, w1h, w1l, w3h, w3l   (80KB)
#define STAGE2_B (TILE_A + 2 * TILE_B2)// A, Bh, Bl               (80KB)
#define SMEM_REQ (2 * STAGE1_B + 1024)

// ---------------- device scratch ----------------
__device__ __half g_x16[(size_t)NT * DDIM];
__device__ __half g_h16[(size_t)NT * HDIM];
__device__ __half g_w1hi[(size_t)NEXP * DDIM * HDIM];  // [e][h][d]
__device__ __half g_w1lo[(size_t)NEXP * DDIM * HDIM];
__device__ __half g_w3hi[(size_t)NEXP * DDIM * HDIM];  // [e][h][d]
__device__ __half g_w3lo[(size_t)NEXP * DDIM * HDIM];
__device__ __half g_w2hi[(size_t)NEXP * HDIM * DDIM];  // [e][d][h]
__device__ __half g_w2lo[(size_t)NEXP * HDIM * DDIM];
__device__ float  g_out[(size_t)NT * DDIM];

__device__ int g_perm[NT];
__device__ int g_slot[NT];
__device__ int g_counter[NEXP];
__device__ int g_tile_e[MAX_TILES];
__device__ int g_tile_row[MAX_TILES];
__device__ int g_tile_end[MAX_TILES];
__device__ int g_num_tiles;

// ---------------- helpers ----------------
__device__ __forceinline__ uint32_t cvta_smem(const void* p) {
    uint32_t a;
    asm("{ .reg .u64 t; cvta.to.shared.u64 t, %1; cvt.u32.u64 %0, t; }" : "=r"(a) : "l"(p));
    return a;
}
static __device__ __forceinline__ uint32_t swz(uint32_t b) { return b ^ ((b >> 3) & 0x70); }

__device__ __forceinline__ void cp16(uint32_t dst, const void* src) {
    asm volatile("cp.async.cg.shared.global [%0], [%1], 16;" :: "r"(dst), "l"(src));
}
__device__ __forceinline__ void cp_commit() {
    asm volatile("cp.async.commit_group;" ::: "memory");
}
__device__ __forceinline__ void ldm_x4(uint32_t* r, uint32_t addr) {
    asm volatile("ldmatrix.sync.aligned.m8n8.x4.shared.b16 {%0,%1,%2,%3}, [%4];"
                 : "=r"(r[0]), "=r"(r[1]), "=r"(r[2]), "=r"(r[3]) : "r"(addr));
}
__device__ __forceinline__ void mma16816(float* d, const uint32_t* a, const uint32_t* b) {
    asm volatile(
        "mma.sync.aligned.m16n8k16.row.col.f32.f16.f16.f32 "
        "{%0,%1,%2,%3}, {%4,%5,%6,%7}, {%8,%9}, {%0,%1,%2,%3};"
        : "+f"(d[0]), "+f"(d[1]), "+f"(d[2]), "+f"(d[3])
        : "r"(a[0]), "r"(a[1]), "r"(a[2]), "r"(a[3]), "r"(b[0]), "r"(b[1]));
}
__device__ __forceinline__ void split_f16(float v, __half& hi, __half& lo) {
    hi = __float2half_rn(v);
    lo = __float2half_rn(v - __half2float(hi));
}

// ---------------- setup / scatter / converts ----------------
__global__ void setup_kernel(const int* __restrict__ bspe) {
    if (threadIdx.x != 0 || blockIdx.x != 0) return;
    int off = 0, t = 0;
    for (int e = 0; e < NEXP; e++) {
        int c = bspe[e];
        g_counter[e] = off;
        int end = off + c;
        for (int r = off; r < end; r += BM) {
            g_tile_e[t] = e; g_tile_row[t] = r; g_tile_end[t] = end; t++;
        }
        off = end;
    }
    g_num_tiles = t;
}

__global__ void scatter_kernel(const int* __restrict__ ei) {
    int t = blockIdx.x * blockDim.x + threadIdx.x;
    if (t < NT) {
        int e = ei[t];
        int p = atomicAdd(&g_counter[e], 1);
        g_perm[p] = t;
        g_slot[t] = p;
    }
}

__global__ void convert_x_kernel(const float* __restrict__ x) {
    int idx = blockIdx.x * 256 + threadIdx.x;
    int p  = idx / (DDIM / 4);
    int c4 = (idx % (DDIM / 4)) * 4;
    int tok = g_perm[p] / TOPK;
    float4 v = *(const float4*)(x + (size_t)tok * DDIM + c4);
    size_t o = (size_t)p * DDIM + c4;
    *(__half2*)(g_x16 + o)     = __floats2half2_rn(v.x, v.y);
    *(__half2*)(g_x16 + o + 2) = __floats2half2_rn(v.z, v.w);
}

// src [E][K][N] fp32 -> dst [E][N][K] fp16 hi/lo (B^T, k contiguous)
template <int W>
__global__ void convert_w_kernel(const float* __restrict__ src) {
    __half* dhi = (W == 0) ? g_w1hi : (W == 1) ? g_w3hi : g_w2hi;
    __half* dlo = (W == 0) ? g_w1lo : (W == 1) ? g_w3lo : g_w2lo;
    __shared__ float s[64][65];
    int e  = blockIdx.z;
    int k0 = blockIdx.x * 64;
    int n0 = blockIdx.y * 64;
    const float* se = src + (size_t)e * 2048 * 2048;
    int tr = threadIdx.x >> 4;
    int tc = (threadIdx.x & 15) * 4;
    #pragma unroll
    for (int i = 0; i < 4; i++) {
        int kl = tr + i * 16;
        float4 v = *(const float4*)(se + (size_t)(k0 + kl) * 2048 + n0 + tc);
        s[kl][tc + 0] = v.x; s[kl][tc + 1] = v.y; s[kl][tc + 2] = v.z; s[kl][tc + 3] = v.w;
    }
    __syncthreads();
    #pragma unroll
    for (int i = 0; i < 4; i++) {
        int nl = tr + i * 16;
        size_t o = ((size_t)e * 2048 + n0 + nl) * 2048 + k0 + tc;
        __half h0, h1, h2, h3, l0, l1, l2, l3;
        split_f16(s[tc + 0][nl], h0, l0);
        split_f16(s[tc + 1][nl], h1, l1);
        split_f16(s[tc + 2][nl], h2, l2);
        split_f16(s[tc + 3][nl], h3, l3);
        *(__half2*)(dhi + o)     = __halves2half2(h0, h1);
        *(__half2*)(dhi + o + 2) = __halves2half2(h2, h3);
        *(__half2*)(dlo + o)     = __halves2half2(l0, l1);
        *(__half2*)(dlo + o + 2) = __halves2half2(l2, l3);
    }
}

// ---------------- GEMM1 (merged): g = x@w1, u = x@w3, h = silu(g)*u ----------
// CTA 128x128, 8 warps 2(m)x4(n), warp tile 64x32, dual accumulators, 2 mma/term.
__global__ void __launch_bounds__(256, 1) gemm1_kernel() {
    int tile = blockIdx.y;
    if (tile >= g_num_tiles) return;
    const int e    = g_tile_e[tile];
    const int row0 = g_tile_row[tile];
    const int rend = g_tile_end[tile];
    const int n0   = blockIdx.x * 128;

    const __half* B1h = g_w1hi + (size_t)e * DDIM * HDIM;
    const __half* B1l = g_w1lo + (size_t)e * DDIM * HDIM;
    const __half* B3h = g_w3hi + (size_t)e * DDIM * HDIM;
    const __half* B3l = g_w3lo + (size_t)e * DDIM * HDIM;

    extern __shared__ char smem[];
    uint32_t sbase = (cvta_smem(smem) + 1023) & ~1023u;

    const int tid  = threadIdx.x;
    const int wid  = tid >> 5;
    const int lane = tid & 31;
    const int wm   = wid & 1;
    const int wn   = wid >> 1;

    auto load_stage = [&](int c) {
        uint32_t st = sbase + (uint32_t)(c & 1) * STAGE1_B;
        int kel = c * BK;
        #pragma unroll
        for (int it = 0; it < 4; it++) {
            int chunk = it * 256 + tid;          // 0..1023
            int row = chunk >> 3;
            int kb  = (chunk & 7) * 16;
            uint32_t so = swz((uint32_t)(row * 128 + kb));
            int ra = row0 + row; if (ra > NT - 1) ra = NT - 1;
            size_t ga = (size_t)ra * 2048 + kel + kb / 2;
            size_t gb = (size_t)(n0 + row) * 2048 + kel + kb / 2;
            cp16(st + 0 * TILE_A + so, g_x16 + ga);
            cp16(st + 1 * TILE_A + so, B1h + gb);
            cp16(st + 2 * TILE_A + so, B1l + gb);
            cp16(st + 3 * TILE_A + so, B3h + gb);
            cp16(st + 4 * TILE_A + so, B3l + gb);
        }
        cp_commit();
    };

    float acc1[4][4][4] = {};
    float acc3[4][4][4] = {};

    const int aRow = lane & 15;
    const int aKof = (lane >> 4) * 16;
    const int bRow = (lane & 7) + ((lane >> 4) & 1) * 8;
    const int bKof = ((lane >> 3) & 1) * 16;

    load_stage(0);
    for (int c = 0; c < NCH; c++) {
        if (c + 1 < NCH) {
            load_stage(c + 1);
            asm volatile("cp.async.wait_group 1;" ::: "memory");
        } else {
            asm volatile("cp.async.wait_group 0;" ::: "memory");
        }
        __syncthreads();

        uint32_t st = sbase + (uint32_t)(c & 1) * STAGE1_B;
        #pragma unroll
        for (int ks = 0; ks < 4; ks++) {
            int kb = ks * 32;
            uint32_t a[4][4];
            #pragma unroll
            for (int mi = 0; mi < 4; mi++) {
                int r = wm * 64 + mi * 16 + aRow;
                uint32_t off = swz((uint32_t)(r * 128 + kb + aKof));
                ldm_x4(a[mi], st + 0 * TILE_A + off);
            }
            #pragma unroll
            for (int p = 0; p < 2; p++) {
                int r = wn * 32 + p * 16 + bRow;
                uint32_t off = swz((uint32_t)(r * 128 + kb + bKof));
                uint32_t th[4], tl[4];
                // ---- w1 ----
                ldm_x4(th, st + 1 * TILE_A + off);
                ldm_x4(tl, st + 2 * TILE_A + off);
                #pragma unroll
                for (int q = 0; q < 2; q++) {
                    uint32_t bh2[2] = { th[2*q], th[2*q+1] };
                    uint32_t bl2[2] = { tl[2*q], tl[2*q+1] };
                    int ni = 2 * p + q;
                    #pragma unroll
                    for (int mi = 0; mi < 4; mi++) {
                        mma16816(acc1[mi][ni], a[mi], bh2);
                        mma16816(acc1[mi][ni], a[mi], bl2);
                    }
                }
                // ---- w3 ----
                ldm_x4(th, st + 3 * TILE_A + off);
                ldm_x4(tl, st + 4 * TILE_A + off);
                #pragma unroll
                for (int q = 0; q < 2; q++) {
                    uint32_t bh2[2] = { th[2*q], th[2*q+1] };
                    uint32_t bl2[2] = { tl[2*q], tl[2*q+1] };
                    int ni = 2 * p + q;
                    #pragma unroll
                    for (int mi = 0; mi < 4; mi++) {
                        mma16816(acc3[mi][ni], a[mi], bh2);
                        mma16816(acc3[mi][ni], a[mi], bl2);
                    }
                }
            }
        }
        __syncthreads();
    }

    // epilogue: h = silu(g) * u -> fp16
    const int erow = lane >> 2;
    const int ecol = (lane & 3) * 2;
    #pragma unroll
    for (int mi = 0; mi < 4; mi++) {
        #pragma unroll
        for (int ni = 0; ni < 4; ni++) {
            int gr0 = row0 + wm * 64 + mi * 16 + erow;
            int gc  = n0 + wn * 32 + ni * 8 + ecol;
            #pragma unroll
            for (int h = 0; h < 2; h++) {
                int gr = gr0 + h * 8;
                if (gr >= rend) continue;
                float gv0 = acc1[mi][ni][h * 2 + 0];
                float gv1 = acc1[mi][ni][h * 2 + 1];
                float uv0 = acc3[mi][ni][h * 2 + 0];
                float uv1 = acc3[mi][ni][h * 2 + 1];
                float h0 = gv0 / (1.0f + __expf(-gv0)) * uv0;
                float h1 = gv1 / (1.0f + __expf(-gv1)) * uv1;
                *(__half2*)(g_h16 + (size_t)gr * 2048 + gc) = __floats2half2_rn(h0, h1);
            }
        }
    }
}

// ---------------- GEMM2: out = h @ w2 (CTA 128x256, warp tile 64x64) --------
__global__ void __launch_bounds__(256, 1) gemm2_kernel() {
    int tile = blockIdx.y;
    if (tile >= g_num_tiles) return;
    const int e    = g_tile_e[tile];
    const int row0 = g_tile_row[tile];
    const int rend = g_tile_end[tile];
    const int n0   = blockIdx.x * 256;

    const __half* Bh = g_w2hi + (size_t)e * HDIM * DDIM;
    const __half* Bl = g_w2lo + (size_t)e * HDIM * DDIM;

    extern __shared__ char smem[];
    uint32_t sbase = (cvta_smem(smem) + 1023) & ~1023u;

    const int tid  = threadIdx.x;
    const int wid  = tid >> 5;
    const int lane = tid & 31;
    const int wm   = wid & 1;
    const int wn   = wid >> 1;

    // stage layout: [0,16K) A, [16K,48K) Bh, [48K,80K) Bl
    auto load_stage = [&](int c) {
        uint32_t st = sbase + (uint32_t)(c & 1) * STAGE2_B;
        int kel = c * BK;
        #pragma unroll
        for (int it = 0; it < 4; it++) {
            int chunk = it * 256 + tid;          // A: 1024 chunks
            int row = chunk >> 3;
            int kb  = (chunk & 7) * 16;
            uint32_t so = swz((uint32_t)(row * 128 + kb));
            int ra = row0 + row; if (ra > NT - 1) ra = NT - 1;
            size_t ga = (size_t)ra * 2048 + kel + kb / 2;
            cp16(st + so, g_h16 + ga);
        }
        #pragma unroll
        for (int it = 0; it < 8; it++) {
            int chunk = it * 256 + tid;          // B: 2048 chunks (256 rows)
            int row = chunk >> 3;
            int kb  = (chunk & 7) * 16;
            uint32_t so = swz((uint32_t)(row * 128 + kb));
            size_t gb = (size_t)(n0 + row) * 2048 + kel + kb / 2;
            cp16(st + TILE_A + so, Bh + gb);
            cp16(st + TILE_A + TILE_B2 + so, Bl + gb);
        }
        cp_commit();
    };

    float acc[4][8][4] = {};

    const int aRow = lane & 15;
    const int aKof = (lane >> 4) * 16;
    const int bRow = (lane & 7) + ((lane >> 4) & 1) * 8;
    const int bKof = ((lane >> 3) & 1) * 16;

    load_stage(0);
    for (int c = 0; c < NCH; c++) {
        if (c + 1 < NCH) {
            load_stage(c + 1);
            asm volatile("cp.async.wait_group 1;" ::: "memory");
        } else {
            asm volatile("cp.async.wait_group 0;" ::: "memory");
        }
        __syncthreads();

        uint32_t st = sbase + (uint32_t)(c & 1) * STAGE2_B;
        #pragma unroll
        for (int ks = 0; ks < 4; ks++) {
            int kb = ks * 32;
            uint32_t a[4][4];
            #pragma unroll
            for (int mi = 0; mi < 4; mi++) {
                int r = wm * 64 + mi * 16 + aRow;
                uint32_t off = swz((uint32_t)(r * 128 + kb + aKof));
                ldm_x4(a[mi], st + off);
            }
            #pragma unroll
            for (int p = 0; p < 4; p++) {
                int r = wn * 64 + p * 16 + bRow;
                uint32_t off = swz((uint32_t)(r * 128 + kb + bKof));
                uint32_t th[4], tl[4];
                ldm_x4(th, st + TILE_A + off);
                ldm_x4(tl, st + TILE_A + TILE_B2 + off);
                #pragma unroll
                for (int q = 0; q < 2; q++) {
                    uint32_t bh2[2] = { th[2*q], th[2*q+1] };
                    uint32_t bl2[2] = { tl[2*q], tl[2*q+1] };
                    int ni = 2 * p + q;
                    #pragma unroll
                    for (int mi = 0; mi < 4; mi++) {
                        mma16816(acc[mi][ni], a[mi], bh2);
                        mma16816(acc[mi][ni], a[mi], bl2);
                    }
                }
            }
        }
        __syncthreads();
    }

    const int erow = lane >> 2;
    const int ecol = (lane & 3) * 2;
    #pragma unroll
    for (int mi = 0; mi < 4; mi++) {
        #pragma unroll
        for (int ni = 0; ni < 8; ni++) {
            int gr0 = row0 + wm * 64 + mi * 16 + erow;
            int gc  = n0 + wn * 64 + ni * 8 + ecol;
            #pragma unroll
            for (int h = 0; h < 2; h++) {
                int gr = gr0 + h * 8;
                if (gr >= rend) continue;
                size_t o = (size_t)gr * 2048 + gc;
                *(float2*)(g_out + o) =
                    make_float2(acc[mi][ni][h * 2 + 0], acc[mi][ni][h * 2 + 1]);
            }
        }
    }
}

// ---------------- combine ----------------
__global__ void combine_kernel(const float* __restrict__ ew, float* __restrict__ y) {
    int i = blockIdx.x * blockDim.x + threadIdx.x;
    const int DQ = DDIM / 4;
    int n  = i / DQ;
    int dq = i % DQ;
    int s0 = g_slot[n * TOPK + 0];
    int s1 = g_slot[n * TOPK + 1];
    float w0 = ew[n * TOPK + 0];
    float w1 = ew[n * TOPK + 1];
    float4 a = *(const float4*)(g_out + (size_t)s0 * DDIM + dq * 4);
    float4 b = *(const float4*)(g_out + (size_t)s1 * DDIM + dq * 4);
    float4 r;
    r.x = w0 * a.x + w1 * b.x;
    r.y = w0 * a.y + w1 * b.y;
    r.z = w0 * a.z + w1 * b.z;
    r.w = w0 * a.w + w1 * b.w;
    ((float4*)y)[i] = r;
}

// ---------------------------------------------------------------------------
extern "C" void kernel_launch(void* const* d_in, const int* in_sizes, int n_in,
                              void* d_out, int out_size) {
    const float* x    = (const float*)d_in[0];
    const float* ew   = (const float*)d_in[1];
    const float* w1   = (const float*)d_in[2];
    const float* w2   = (const float*)d_in[3];
    const float* w3   = (const float*)d_in[4];
    const int*   ei   = (const int*)d_in[5];
    const int*   bspe = (const int*)d_in[6];
    float* y = (float*)d_out;

    cudaFuncSetAttribute(gemm1_kernel, cudaFuncAttributeMaxDynamicSharedMemorySize, SMEM_REQ);
    cudaFuncSetAttribute(gemm2_kernel, cudaFuncAttributeMaxDynamicSharedMemorySize, SMEM_REQ);

    setup_kernel<<<1, 32>>>(bspe);
    scatter_kernel<<<NT / 256, 256>>>(ei);
    convert_x_kernel<<<(NT * DDIM / 4) / 256, 256>>>(x);

    dim3 wgrid(32, 32, NEXP);
    convert_w_kernel<0><<<wgrid, 256>>>(w1);
    convert_w_kernel<1><<<wgrid, 256>>>(w3);
    convert_w_kernel<2><<<wgrid, 256>>>(w2);

    dim3 g1(HDIM / 128, MAX_TILES);
    gemm1_kernel<<<g1, 256, SMEM_REQ>>>();
    dim3 g2(DDIM / 256, MAX_TILES);
    gemm2_kernel<<<g2, 256, SMEM_REQ>>>();

    combine_kernel<<<(N_TOK * DDIM / 4) / 256, 256>>>(ew, y);
}

// round 7
// speedup vs baseline: 8.2592x; 1.6564x over previous
#include <cuda_runtime.h>
#include <cuda_bf16.h>
#include <cuda_fp16.h>
#include <math.h>
#include <stdint.h>

// ---------------- problem constants ----------------
#define N_TOK 8192
#define DDIM  2048
#define HDIM  2048
#define NEXP  8
#define TOPK  2
#define NT    (N_TOK * TOPK)          // 16384 token-copies

#define BM 128
#define BK 64                          // fp16 elems per stage (128 bytes/row)
#define NCH (DDIM / BK)                // 32 k-stages
#define MAX_TILES (NT / BM + NEXP)     // 136

#define TILE_A   16384                 // 128 rows x 128B
#define TILE_B2  32768                 // 256 rows x 128B
#define STAGE1_B (3 * TILE_A)          // A, w1, w3          (48KB)
#define STAGE2_B (TILE_A + TILE_B2)    // A, B               (48KB)
#define NB 3                           // pipeline buffers
#define SMEM_REQ (NB * STAGE1_B + 1024)

// ---------------- device scratch ----------------
__device__ __half g_x16[(size_t)NT * DDIM];
__device__ __half g_h16[(size_t)NT * HDIM];
__device__ __half g_w1[(size_t)NEXP * DDIM * HDIM];  // [e][h][d]
__device__ __half g_w3[(size_t)NEXP * DDIM * HDIM];  // [e][h][d]
__device__ __half g_w2[(size_t)NEXP * HDIM * DDIM];  // [e][d][h]
__device__ float  g_out[(size_t)NT * DDIM];

__device__ int g_perm[NT];
__device__ int g_slot[NT];
__device__ int g_counter[NEXP];
__device__ int g_tile_e[MAX_TILES];
__device__ int g_tile_row[MAX_TILES];
__device__ int g_tile_end[MAX_TILES];
__device__ int g_num_tiles;

// ---------------- helpers ----------------
__device__ __forceinline__ uint32_t cvta_smem(const void* p) {
    uint32_t a;
    asm("{ .reg .u64 t; cvta.to.shared.u64 t, %1; cvt.u32.u64 %0, t; }" : "=r"(a) : "l"(p));
    return a;
}
static __device__ __forceinline__ uint32_t swz(uint32_t b) { return b ^ ((b >> 3) & 0x70); }

__device__ __forceinline__ void cp16(uint32_t dst, const void* src) {
    asm volatile("cp.async.cg.shared.global [%0], [%1], 16;" :: "r"(dst), "l"(src));
}
__device__ __forceinline__ void cp_commit() {
    asm volatile("cp.async.commit_group;" ::: "memory");
}
__device__ __forceinline__ void ldm_x4(uint32_t* r, uint32_t addr) {
    asm volatile("ldmatrix.sync.aligned.m8n8.x4.shared.b16 {%0,%1,%2,%3}, [%4];"
                 : "=r"(r[0]), "=r"(r[1]), "=r"(r[2]), "=r"(r[3]) : "r"(addr));
}
__device__ __forceinline__ void mma16816(float* d, const uint32_t* a, const uint32_t* b) {
    asm volatile(
        "mma.sync.aligned.m16n8k16.row.col.f32.f16.f16.f32 "
        "{%0,%1,%2,%3}, {%4,%5,%6,%7}, {%8,%9}, {%0,%1,%2,%3};"
        : "+f"(d[0]), "+f"(d[1]), "+f"(d[2]), "+f"(d[3])
        : "r"(a[0]), "r"(a[1]), "r"(a[2]), "r"(a[3]), "r"(b[0]), "r"(b[1]));
}

// ---------------- setup / scatter / converts ----------------
__global__ void setup_kernel(const int* __restrict__ bspe) {
    if (threadIdx.x != 0 || blockIdx.x != 0) return;
    int off = 0, t = 0;
    for (int e = 0; e < NEXP; e++) {
        int c = bspe[e];
        g_counter[e] = off;
        int end = off + c;
        for (int r = off; r < end; r += BM) {
            g_tile_e[t] = e; g_tile_row[t] = r; g_tile_end[t] = end; t++;
        }
        off = end;
    }
    g_num_tiles = t;
}

__global__ void scatter_kernel(const int* __restrict__ ei) {
    int t = blockIdx.x * blockDim.x + threadIdx.x;
    if (t < NT) {
        int e = ei[t];
        int p = atomicAdd(&g_counter[e], 1);
        g_perm[p] = t;
        g_slot[t] = p;
    }
}

__global__ void convert_x_kernel(const float* __restrict__ x) {
    int idx = blockIdx.x * 256 + threadIdx.x;
    int p  = idx / (DDIM / 4);
    int c4 = (idx % (DDIM / 4)) * 4;
    int tok = g_perm[p] / TOPK;
    float4 v = *(const float4*)(x + (size_t)tok * DDIM + c4);
    size_t o = (size_t)p * DDIM + c4;
    *(__half2*)(g_x16 + o)     = __floats2half2_rn(v.x, v.y);
    *(__half2*)(g_x16 + o + 2) = __floats2half2_rn(v.z, v.w);
}

// src [E][K][N] fp32 -> dst [E][N][K] fp16 (B^T, k contiguous)
template <int W>
__global__ void convert_w_kernel(const float* __restrict__ src) {
    __half* dst = (W == 0) ? g_w1 : (W == 1) ? g_w3 : g_w2;
    __shared__ float s[64][65];
    int e  = blockIdx.z;
    int k0 = blockIdx.x * 64;
    int n0 = blockIdx.y * 64;
    const float* se = src + (size_t)e * 2048 * 2048;
    int tr = threadIdx.x >> 4;
    int tc = (threadIdx.x & 15) * 4;
    #pragma unroll
    for (int i = 0; i < 4; i++) {
        int kl = tr + i * 16;
        float4 v = *(const float4*)(se + (size_t)(k0 + kl) * 2048 + n0 + tc);
        s[kl][tc + 0] = v.x; s[kl][tc + 1] = v.y; s[kl][tc + 2] = v.z; s[kl][tc + 3] = v.w;
    }
    __syncthreads();
    #pragma unroll
    for (int i = 0; i < 4; i++) {
        int nl = tr + i * 16;
        size_t o = ((size_t)e * 2048 + n0 + nl) * 2048 + k0 + tc;
        *(__half2*)(dst + o)     = __floats2half2_rn(s[tc + 0][nl], s[tc + 1][nl]);
        *(__half2*)(dst + o + 2) = __floats2half2_rn(s[tc + 2][nl], s[tc + 3][nl]);
    }
}

// ---------------- GEMM1 (merged): g = x@w1, u = x@w3, h = silu(g)*u ----------
// CTA 128x128, 8 warps 2(m)x4(n), warp tile 64x32, 3-buffer pipeline, 1 sync/iter.
__global__ void __launch_bounds__(256, 1) gemm1_kernel() {
    int tile = blockIdx.y;
    if (tile >= g_num_tiles) return;
    const int e    = g_tile_e[tile];
    const int row0 = g_tile_row[tile];
    const int rend = g_tile_end[tile];
    const int n0   = blockIdx.x * 128;

    const __half* B1 = g_w1 + (size_t)e * DDIM * HDIM;
    const __half* B3 = g_w3 + (size_t)e * DDIM * HDIM;

    extern __shared__ char smem[];
    uint32_t sbase = (cvta_smem(smem) + 1023) & ~1023u;

    const int tid  = threadIdx.x;
    const int wid  = tid >> 5;
    const int lane = tid & 31;
    const int wm   = wid & 1;
    const int wn   = wid >> 1;

    auto load_stage = [&](int c) {
        uint32_t st = sbase + (uint32_t)(c % NB) * STAGE1_B;
        int kel = c * BK;
        #pragma unroll
        for (int it = 0; it < 4; it++) {
            int chunk = it * 256 + tid;          // 0..1023
            int row = chunk >> 3;
            int kb  = (chunk & 7) * 16;
            uint32_t so = swz((uint32_t)(row * 128 + kb));
            int ra = row0 + row; if (ra > NT - 1) ra = NT - 1;
            size_t ga = (size_t)ra * 2048 + kel + kb / 2;
            size_t gb = (size_t)(n0 + row) * 2048 + kel + kb / 2;
            cp16(st + 0 * TILE_A + so, g_x16 + ga);
            cp16(st + 1 * TILE_A + so, B1 + gb);
            cp16(st + 2 * TILE_A + so, B3 + gb);
        }
        cp_commit();
    };

    float acc1[4][4][4] = {};
    float acc3[4][4][4] = {};

    const int aRow = lane & 15;
    const int aKof = (lane >> 4) * 16;
    const int bRow = (lane & 7) + ((lane >> 4) & 1) * 8;
    const int bKof = ((lane >> 3) & 1) * 16;

    load_stage(0);
    load_stage(1);
    for (int c = 0; c < NCH; c++) {
        if (c + 1 < NCH) {
            asm volatile("cp.async.wait_group 1;" ::: "memory");
        } else {
            asm volatile("cp.async.wait_group 0;" ::: "memory");
        }
        __syncthreads();
        if (c + 2 < NCH) load_stage(c + 2);

        uint32_t st = sbase + (uint32_t)(c % NB) * STAGE1_B;
        #pragma unroll
        for (int ks = 0; ks < 4; ks++) {
            int kb = ks * 32;
            uint32_t a[4][4];
            #pragma unroll
            for (int mi = 0; mi < 4; mi++) {
                int r = wm * 64 + mi * 16 + aRow;
                uint32_t off = swz((uint32_t)(r * 128 + kb + aKof));
                ldm_x4(a[mi], st + 0 * TILE_A + off);
            }
            #pragma unroll
            for (int p = 0; p < 2; p++) {
                int r = wn * 32 + p * 16 + bRow;
                uint32_t off = swz((uint32_t)(r * 128 + kb + bKof));
                uint32_t t1[4], t3[4];
                ldm_x4(t1, st + 1 * TILE_A + off);
                ldm_x4(t3, st + 2 * TILE_A + off);
                #pragma unroll
                for (int q = 0; q < 2; q++) {
                    uint32_t b1[2] = { t1[2*q], t1[2*q+1] };
                    uint32_t b3[2] = { t3[2*q], t3[2*q+1] };
                    int ni = 2 * p + q;
                    #pragma unroll
                    for (int mi = 0; mi < 4; mi++) {
                        mma16816(acc1[mi][ni], a[mi], b1);
                        mma16816(acc3[mi][ni], a[mi], b3);
                    }
                }
            }
        }
    }

    // epilogue: h = silu(g) * u -> fp16
    const int erow = lane >> 2;
    const int ecol = (lane & 3) * 2;
    #pragma unroll
    for (int mi = 0; mi < 4; mi++) {
        #pragma unroll
        for (int ni = 0; ni < 4; ni++) {
            int gr0 = row0 + wm * 64 + mi * 16 + erow;
            int gc  = n0 + wn * 32 + ni * 8 + ecol;
            #pragma unroll
            for (int h = 0; h < 2; h++) {
                int gr = gr0 + h * 8;
                if (gr >= rend) continue;
                float gv0 = acc1[mi][ni][h * 2 + 0];
                float gv1 = acc1[mi][ni][h * 2 + 1];
                float uv0 = acc3[mi][ni][h * 2 + 0];
                float uv1 = acc3[mi][ni][h * 2 + 1];
                float h0 = gv0 / (1.0f + __expf(-gv0)) * uv0;
                float h1 = gv1 / (1.0f + __expf(-gv1)) * uv1;
                *(__half2*)(g_h16 + (size_t)gr * 2048 + gc) = __floats2half2_rn(h0, h1);
            }
        }
    }
}

// ---------------- GEMM2: out = h @ w2 (CTA 128x256, warp tile 64x64) --------
__global__ void __launch_bounds__(256, 1) gemm2_kernel() {
    int tile = blockIdx.y;
    if (tile >= g_num_tiles) return;
    const int e    = g_tile_e[tile];
    const int row0 = g_tile_row[tile];
    const int rend = g_tile_end[tile];
    const int n0   = blockIdx.x * 256;

    const __half* B = g_w2 + (size_t)e * HDIM * DDIM;

    extern __shared__ char smem[];
    uint32_t sbase = (cvta_smem(smem) + 1023) & ~1023u;

    const int tid  = threadIdx.x;
    const int wid  = tid >> 5;
    const int lane = tid & 31;
    const int wm   = wid & 1;
    const int wn   = wid >> 1;

    // stage layout: [0,16K) A, [16K,48K) B
    auto load_stage = [&](int c) {
        uint32_t st = sbase + (uint32_t)(c % NB) * STAGE2_B;
        int kel = c * BK;
        #pragma unroll
        for (int it = 0; it < 4; it++) {
            int chunk = it * 256 + tid;          // A: 1024 chunks
            int row = chunk >> 3;
            int kb  = (chunk & 7) * 16;
            uint32_t so = swz((uint32_t)(row * 128 + kb));
            int ra = row0 + row; if (ra > NT - 1) ra = NT - 1;
            size_t ga = (size_t)ra * 2048 + kel + kb / 2;
            cp16(st + so, g_h16 + ga);
        }
        #pragma unroll
        for (int it = 0; it < 8; it++) {
            int chunk = it * 256 + tid;          // B: 2048 chunks (256 rows)
            int row = chunk >> 3;
            int kb  = (chunk & 7) * 16;
            uint32_t so = swz((uint32_t)(row * 128 + kb));
            size_t gb = (size_t)(n0 + row) * 2048 + kel + kb / 2;
            cp16(st + TILE_A + so, B + gb);
        }
        cp_commit();
    };

    float acc[4][8][4] = {};

    const int aRow = lane & 15;
    const int aKof = (lane >> 4) * 16;
    const int bRow = (lane & 7) + ((lane >> 4) & 1) * 8;
    const int bKof = ((lane >> 3) & 1) * 16;

    load_stage(0);
    load_stage(1);
    for (int c = 0; c < NCH; c++) {
        if (c + 1 < NCH) {
            asm volatile("cp.async.wait_group 1;" ::: "memory");
        } else {
            asm volatile("cp.async.wait_group 0;" ::: "memory");
        }
        __syncthreads();
        if (c + 2 < NCH) load_stage(c + 2);

        uint32_t st = sbase + (uint32_t)(c % NB) * STAGE2_B;
        #pragma unroll
        for (int ks = 0; ks < 4; ks++) {
            int kb = ks * 32;
            uint32_t a[4][4];
            #pragma unroll
            for (int mi = 0; mi < 4; mi++) {
                int r = wm * 64 + mi * 16 + aRow;
                uint32_t off = swz((uint32_t)(r * 128 + kb + aKof));
                ldm_x4(a[mi], st + off);
            }
            #pragma unroll
            for (int p = 0; p < 4; p++) {
                int r = wn * 64 + p * 16 + bRow;
                uint32_t off = swz((uint32_t)(r * 128 + kb + bKof));
                uint32_t tb[4];
                ldm_x4(tb, st + TILE_A + off);
                #pragma unroll
                for (int q = 0; q < 2; q++) {
                    uint32_t b2[2] = { tb[2*q], tb[2*q+1] };
                    int ni = 2 * p + q;
                    #pragma unroll
                    for (int mi = 0; mi < 4; mi++) {
                        mma16816(acc[mi][ni], a[mi], b2);
                    }
                }
            }
        }
    }

    const int erow = lane >> 2;
    const int ecol = (lane & 3) * 2;
    #pragma unroll
    for (int mi = 0; mi < 4; mi++) {
        #pragma unroll
        for (int ni = 0; ni < 8; ni++) {
            int gr0 = row0 + wm * 64 + mi * 16 + erow;
            int gc  = n0 + wn * 64 + ni * 8 + ecol;
            #pragma unroll
            for (int h = 0; h < 2; h++) {
                int gr = gr0 + h * 8;
                if (gr >= rend) continue;
                size_t o = (size_t)gr * 2048 + gc;
                *(float2*)(g_out + o) =
                    make_float2(acc[mi][ni][h * 2 + 0], acc[mi][ni][h * 2 + 1]);
            }
        }
    }
}

// ---------------- combine ----------------
__global__ void combine_kernel(const float* __restrict__ ew, float* __restrict__ y) {
    int i = blockIdx.x * blockDim.x + threadIdx.x;
    const int DQ = DDIM / 4;
    int n  = i / DQ;
    int dq = i % DQ;
    int s0 = g_slot[n * TOPK + 0];
    int s1 = g_slot[n * TOPK + 1];
    float w0 = ew[n * TOPK + 0];
    float w1 = ew[n * TOPK + 1];
    float4 a = *(const float4*)(g_out + (size_t)s0 * DDIM + dq * 4);
    float4 b = *(const float4*)(g_out + (size_t)s1 * DDIM + dq * 4);
    float4 r;
    r.x = w0 * a.x + w1 * b.x;
    r.y = w0 * a.y + w1 * b.y;
    r.z = w0 * a.z + w1 * b.z;
    r.w = w0 * a.w + w1 * b.w;
    ((float4*)y)[i] = r;
}

// ---------------------------------------------------------------------------
extern "C" void kernel_launch(void* const* d_in, const int* in_sizes, int n_in,
                              void* d_out, int out_size) {
    const float* x    = (const float*)d_in[0];
    const float* ew   = (const float*)d_in[1];
    const float* w1   = (const float*)d_in[2];
    const float* w2   = (const float*)d_in[3];
    const float* w3   = (const float*)d_in[4];
    const int*   ei   = (const int*)d_in[5];
    const int*   bspe = (const int*)d_in[6];
    float* y = (float*)d_out;

    cudaFuncSetAttribute(gemm1_kernel, cudaFuncAttributeMaxDynamicSharedMemorySize, SMEM_REQ);
    cudaFuncSetAttribute(gemm2_kernel, cudaFuncAttributeMaxDynamicSharedMemorySize, SMEM_REQ);

    setup_kernel<<<1, 32>>>(bspe);
    scatter_kernel<<<NT / 256, 256>>>(ei);
    convert_x_kernel<<<(NT * DDIM / 4) / 256, 256>>>(x);

    dim3 wgrid(32, 32, NEXP);
    convert_w_kernel<0><<<wgrid, 256>>>(w1);
    convert_w_kernel<1><<<wgrid, 256>>>(w3);
    convert_w_kernel<2><<<wgrid, 256>>>(w2);

    dim3 g1(HDIM / 128, MAX_TILES);
    gemm1_kernel<<<g1, 256, SMEM_REQ>>>();
    dim3 g2(DDIM / 256, MAX_TILES);
    gemm2_kernel<<<g2, 256, SMEM_REQ>>>();

    combine_kernel<<<(N_TOK * DDIM / 4) / 256, 256>>>(ew, y);
}